// round 11
// baseline (speedup 1.0000x reference)
#include <cuda_runtime.h>
#include <math.h>

#define HEADS   8
#define DFUSED  480
#define E_MAX   262144
#define N_MAX   16384

// Scratch (no device allocation allowed -> __device__ globals)
__device__ float g_ew[(size_t)E_MAX * HEADS];  // exp(w) per (edge, head)
__device__ int   g_cnt[N_MAX + 1];             // per-node edge counts
__device__ int   g_rowstart[N_MAX + 1];        // CSR row offsets
__device__ int   g_off[N_MAX];                 // atomic fill cursors
__device__ int   g_perm[E_MAX];                // edge ids grouped by dst node
__device__ int   g_is64;                       // edge_index dtype flag

// head of fused feature index j (block sizes 128/192/160; head strides 16/24/20)
__device__ __forceinline__ int head_of(int j) {
    return (j < 128) ? (j >> 4) : ((j < 320) ? (j - 128) / 24 : (j - 320) / 20);
}

// dtype-agnostic load of edge_index[1][e] (dst node), clamped to [0, N)
__device__ __forceinline__ int load_dst(const void* ei, int E, int e, int N) {
    int d;
    if (g_is64) d = (int)((const long long*)ei)[(size_t)E + e];
    else        d = ((const int*)ei)[E + e];
    d = d < 0 ? 0 : (d >= N ? N - 1 : d);
    return d;
}

// ---------------------------------------------------------------------------
// Kernel A: probe edge_index dtype (block 0) + zero g_cnt.
// int64 values < 2^31 -> int32 view has zeros at every odd word.
// ---------------------------------------------------------------------------
__global__ void initA_kernel(const unsigned int* __restrict__ ei, int E, int N) {
    if (blockIdx.x == 0) {
        __shared__ int nz;
        if (threadIdx.x == 0) nz = 0;
        __syncthreads();
        int lim = 2 * E < 512 ? 2 * E : 512;
        for (int i = threadIdx.x; i < lim; i += blockDim.x)
            if ((i & 1) && ei[i] != 0u) atomicAdd(&nz, 1);
        __syncthreads();
        if (threadIdx.x == 0) g_is64 = (nz == 0) ? 1 : 0;
    }
    int stride = gridDim.x * blockDim.x;
    for (int i = blockIdx.x * blockDim.x + threadIdx.x; i <= N; i += stride)
        g_cnt[i] = 0;
}

// ---------------------------------------------------------------------------
// Kernel B: histogram of destination nodes
// ---------------------------------------------------------------------------
__global__ void hist_kernel(const void* __restrict__ eidx, int E, int N) {
    int e = blockIdx.x * blockDim.x + threadIdx.x;
    if (e >= E) return;
    atomicAdd(&g_cnt[load_dst(eidx, E, e, N)], 1);
}

// ---------------------------------------------------------------------------
// Kernel C: exclusive scan of counts -> row offsets (single block, 1024 thr)
// ---------------------------------------------------------------------------
__global__ void __launch_bounds__(1024)
scan_kernel(int N) {
    __shared__ int wsum[32];
    __shared__ int s_total;
    int tid = threadIdx.x, lane = tid & 31, wid = tid >> 5;
    int running = 0;
    for (int base = 0; base < N; base += 1024) {
        int i = base + tid;
        int x = (i < N) ? g_cnt[i] : 0;
        int incl = x;
        #pragma unroll
        for (int d = 1; d < 32; d <<= 1) {
            int y = __shfl_up_sync(0xffffffffu, incl, d);
            if (lane >= d) incl += y;
        }
        if (lane == 31) wsum[wid] = incl;
        __syncthreads();
        if (wid == 0) {
            int w = wsum[lane], wi = w;
            #pragma unroll
            for (int d = 1; d < 32; d <<= 1) {
                int y = __shfl_up_sync(0xffffffffu, wi, d);
                if (lane >= d) wi += y;
            }
            wsum[lane] = wi - w;   // exclusive warp offset
        }
        __syncthreads();
        int excl = running + wsum[wid] + incl - x;
        if (i < N) { g_rowstart[i] = excl; g_off[i] = excl; }
        if (tid == 1023) s_total = excl + x;
        __syncthreads();
        running = s_total;
        __syncthreads();
    }
    if (tid == 0) g_rowstart[N] = running;
}

// ---------------------------------------------------------------------------
// Kernel D: permutation — edge ids grouped by destination node
// ---------------------------------------------------------------------------
__global__ void perm_kernel(const void* __restrict__ eidx, int E, int N) {
    int e = blockIdx.x * blockDim.x + threadIdx.x;
    if (e >= E) return;
    int pos = atomicAdd(&g_off[load_dst(eidx, E, e, N)], 1);
    g_perm[pos] = e;
}

// ---------------------------------------------------------------------------
// Kernel 1: edge-parallel logits — pure streaming, no atomics beyond smem.
// One warp per edge: read q,k rows (float4 coalesced), per-head dot via smem
// atomicAdd, write ew = exp(cutoff*dot/sqrt(60)) as 8 floats (32B store).
// Max-shift dropped: softmax is shift-invariant; logits here are O(5).
// ---------------------------------------------------------------------------
__global__ void __launch_bounds__(256)
logits_kernel(const float* __restrict__ q, const float* __restrict__ k,
              const float* __restrict__ cutoff, int E) {
    __shared__ float sh[8][HEADS];
    int e    = (blockIdx.x * blockDim.x + threadIdx.x) >> 5;
    int lane = threadIdx.x & 31;
    int wl   = threadIdx.x >> 5;
    if (e >= E) return;

    if (lane < HEADS) sh[wl][lane] = 0.0f;
    __syncwarp();

    const float4* q4 = (const float4*)(q + (size_t)e * DFUSED);
    const float4* k4 = (const float4*)(k + (size_t)e * DFUSED);

    #pragma unroll
    for (int t = 0; t < 4; t++) {
        int i4 = lane + 32 * t;
        if (i4 < 120) {
            float4 a = q4[i4];
            float4 b = k4[i4];
            float p = a.x * b.x + a.y * b.y + a.z * b.z + a.w * b.w;
            atomicAdd(&sh[wl][head_of(i4 * 4)], p);
        }
    }
    __syncwarp();

    if (lane < HEADS) {
        float wv = cutoff[e] * sh[wl][lane] * 0.12909944487358056f; // 1/sqrt(60)
        g_ew[(size_t)e * HEADS + lane] = __expf(wv);
    }
}

// ---------------------------------------------------------------------------
// Kernel 2: node-parallel gather of values. One warp per node.
// Loop body has NO syncwarp / NO shared memory: per edge, 4 independent
// LDG.128 of the v row + one 4B ew load (lane<8), shfl broadcast, register
// FMA accumulation. Iterations pipeline freely (loads of i+1 overlap i).
// ssum accumulated in-register -> no g_s, no separate normalize pass.
// ---------------------------------------------------------------------------
__global__ void __launch_bounds__(256)
gather_kernel(const float* __restrict__ v, float* __restrict__ out, int N) {
    int warp = (blockIdx.x * blockDim.x + threadIdx.x) >> 5;
    int lane = threadIdx.x & 31;
    if (warp >= N) return;

    int beg = g_rowstart[warp];
    int end = g_rowstart[warp + 1];

    // head owning each of this lane's 4 float4 slots (also the shfl src lane)
    int hl[4];
    #pragma unroll
    for (int t = 0; t < 4; t++) {
        int i4 = lane + 32 * t;
        hl[t] = head_of((i4 < 120 ? i4 : 119) * 4);
    }

    float4 acc[4];
    #pragma unroll
    for (int t = 0; t < 4; t++) acc[t] = make_float4(0.f, 0.f, 0.f, 0.f);
    float ssum = 0.0f;   // lane h (<8) accumulates sum of ew for head h

    #pragma unroll 2
    for (int i = beg; i < end; i++) {
        int e = g_perm[i];
        float ewl = (lane < HEADS) ? g_ew[(size_t)e * HEADS + lane] : 0.0f;
        const float4* v4 = (const float4*)(v + (size_t)e * DFUSED);

        #pragma unroll
        for (int t = 0; t < 4; t++) {
            float c = __shfl_sync(0xffffffffu, ewl, hl[t]);
            int i4 = lane + 32 * t;
            if (i4 < 120) {
                float4 vv = v4[i4];
                acc[t].x += c * vv.x;
                acc[t].y += c * vv.y;
                acc[t].z += c * vv.z;
                acc[t].w += c * vv.w;
            }
        }
        ssum += ewl;
    }

    // normalize + single coalesced write of the output row
    float4* o4 = (float4*)(out + (size_t)warp * DFUSED);
    #pragma unroll
    for (int t = 0; t < 4; t++) {
        float sv  = __shfl_sync(0xffffffffu, ssum, hl[t]);
        float inv = 1.0f / (sv + 1e-16f);
        int i4 = lane + 32 * t;
        if (i4 < 120) {
            float4 r;
            r.x = acc[t].x * inv; r.y = acc[t].y * inv;
            r.z = acc[t].z * inv; r.w = acc[t].w * inv;
            o4[i4] = r;
        }
    }
}

// ---------------------------------------------------------------------------
extern "C" void kernel_launch(void* const* d_in, const int* in_sizes, int n_in,
                              void* d_out, int out_size) {
    // Classify inputs by element count (robust to scalar inputs):
    //   3 buffers of size 480*E -> key, value, query (relative order preserved)
    //   1 buffer of size E      -> edge_weight_cutoff
    //   1 buffer of size 2*E    -> edge_index
    long long mx = 0;
    for (int i = 0; i < n_in; i++)
        if ((long long)in_sizes[i] > mx) mx = in_sizes[i];
    int E = (int)(mx / DFUSED);

    const float* big[3] = {0, 0, 0};
    const float* cutoff = 0;
    const void*  eidx   = 0;
    int nbig = 0;
    for (int i = 0; i < n_in; i++) {
        long long s = in_sizes[i];
        if (s == mx && nbig < 3)      big[nbig++] = (const float*)d_in[i];
        else if (s == (long long)E)   cutoff = (const float*)d_in[i];
        else if (s == 2LL * E)        eidx   = d_in[i];
    }
    const float* key   = big[0];
    const float* value = big[1];
    const float* query = big[2];

    int N = out_size / DFUSED;
    float* out = (float*)d_out;

    initA_kernel<<<64, 256>>>((const unsigned int*)eidx, E, N);
    hist_kernel<<<(E + 255) / 256, 256>>>(eidx, E, N);
    scan_kernel<<<1, 1024>>>(N);
    perm_kernel<<<(E + 255) / 256, 256>>>(eidx, E, N);
    logits_kernel<<<(E + 7) / 8, 256>>>(query, key, cutoff, E);
    gather_kernel<<<(N + 7) / 8, 256>>>(value, out, N);
}

// round 12
// speedup vs baseline: 1.0067x; 1.0067x over previous
#include <cuda_runtime.h>
#include <math.h>

#define HEADS   8
#define DFUSED  480
#define E_MAX   262144
#define N_MAX   16384

// Scratch (no device allocation allowed -> __device__ globals)
__device__ float g_ew[(size_t)E_MAX * HEADS];  // exp(w) per (edge, head)
__device__ int   g_cnt[N_MAX + 1];             // per-node edge counts
__device__ int   g_rowstart[N_MAX + 1];        // CSR row offsets
__device__ int   g_off[N_MAX];                 // atomic fill cursors
__device__ int   g_perm[E_MAX];                // edge ids grouped by dst node
__device__ int   g_is64;                       // edge_index dtype flag

// head of fused feature index j (block sizes 128/192/160; head strides 16/24/20)
__device__ __forceinline__ int head_of(int j) {
    return (j < 128) ? (j >> 4) : ((j < 320) ? (j - 128) / 24 : (j - 320) / 20);
}

// dtype-agnostic load of edge_index[1][e] (dst node), clamped to [0, N)
__device__ __forceinline__ int load_dst(const void* ei, int E, int e, int N) {
    int d;
    if (g_is64) d = (int)((const long long*)ei)[(size_t)E + e];
    else        d = ((const int*)ei)[E + e];
    d = d < 0 ? 0 : (d >= N ? N - 1 : d);
    return d;
}

// ---------------------------------------------------------------------------
// Kernel A: probe edge_index dtype (block 0) + zero g_cnt.
// int64 values < 2^31 -> int32 view has zeros at every odd word.
// ---------------------------------------------------------------------------
__global__ void initA_kernel(const unsigned int* __restrict__ ei, int E, int N) {
    if (blockIdx.x == 0) {
        __shared__ int nz;
        if (threadIdx.x == 0) nz = 0;
        __syncthreads();
        int lim = 2 * E < 512 ? 2 * E : 512;
        for (int i = threadIdx.x; i < lim; i += blockDim.x)
            if ((i & 1) && ei[i] != 0u) atomicAdd(&nz, 1);
        __syncthreads();
        if (threadIdx.x == 0) g_is64 = (nz == 0) ? 1 : 0;
    }
    int stride = gridDim.x * blockDim.x;
    for (int i = blockIdx.x * blockDim.x + threadIdx.x; i <= N; i += stride)
        g_cnt[i] = 0;
}

// ---------------------------------------------------------------------------
// Kernel B: histogram of destination nodes
// ---------------------------------------------------------------------------
__global__ void hist_kernel(const void* __restrict__ eidx, int E, int N) {
    int e = blockIdx.x * blockDim.x + threadIdx.x;
    if (e >= E) return;
    atomicAdd(&g_cnt[load_dst(eidx, E, e, N)], 1);
}

// ---------------------------------------------------------------------------
// Kernel C: exclusive scan of counts -> row offsets (single block, 1024 thr)
// ---------------------------------------------------------------------------
__global__ void __launch_bounds__(1024)
scan_kernel(int N) {
    __shared__ int wsum[32];
    __shared__ int s_total;
    int tid = threadIdx.x, lane = tid & 31, wid = tid >> 5;
    int running = 0;
    for (int base = 0; base < N; base += 1024) {
        int i = base + tid;
        int x = (i < N) ? g_cnt[i] : 0;
        int incl = x;
        #pragma unroll
        for (int d = 1; d < 32; d <<= 1) {
            int y = __shfl_up_sync(0xffffffffu, incl, d);
            if (lane >= d) incl += y;
        }
        if (lane == 31) wsum[wid] = incl;
        __syncthreads();
        if (wid == 0) {
            int w = wsum[lane], wi = w;
            #pragma unroll
            for (int d = 1; d < 32; d <<= 1) {
                int y = __shfl_up_sync(0xffffffffu, wi, d);
                if (lane >= d) wi += y;
            }
            wsum[lane] = wi - w;   // exclusive warp offset
        }
        __syncthreads();
        int excl = running + wsum[wid] + incl - x;
        if (i < N) { g_rowstart[i] = excl; g_off[i] = excl; }
        if (tid == 1023) s_total = excl + x;
        __syncthreads();
        running = s_total;
        __syncthreads();
    }
    if (tid == 0) g_rowstart[N] = running;
}

// ---------------------------------------------------------------------------
// Kernel D: permutation — edge ids grouped by destination node
// ---------------------------------------------------------------------------
__global__ void perm_kernel(const void* __restrict__ eidx, int E, int N) {
    int e = blockIdx.x * blockDim.x + threadIdx.x;
    if (e >= E) return;
    int pos = atomicAdd(&g_off[load_dst(eidx, E, e, N)], 1);
    g_perm[pos] = e;
}

// ---------------------------------------------------------------------------
// Kernel 1: edge-parallel logits — pure streaming, no atomics beyond smem.
// One warp per edge: read q,k rows (float4 coalesced), per-head dot via smem
// atomicAdd, write ew = exp(cutoff*dot/sqrt(60)) as 8 floats (32B store).
// Max-shift dropped: softmax is shift-invariant; logits here are O(5).
// ---------------------------------------------------------------------------
__global__ void __launch_bounds__(256)
logits_kernel(const float* __restrict__ q, const float* __restrict__ k,
              const float* __restrict__ cutoff, int E) {
    __shared__ float sh[8][HEADS];
    int e    = (blockIdx.x * blockDim.x + threadIdx.x) >> 5;
    int lane = threadIdx.x & 31;
    int wl   = threadIdx.x >> 5;
    if (e >= E) return;

    if (lane < HEADS) sh[wl][lane] = 0.0f;
    __syncwarp();

    const float4* q4 = (const float4*)(q + (size_t)e * DFUSED);
    const float4* k4 = (const float4*)(k + (size_t)e * DFUSED);

    #pragma unroll
    for (int t = 0; t < 4; t++) {
        int i4 = lane + 32 * t;
        if (i4 < 120) {
            float4 a = q4[i4];
            float4 b = k4[i4];
            float p = a.x * b.x + a.y * b.y + a.z * b.z + a.w * b.w;
            atomicAdd(&sh[wl][head_of(i4 * 4)], p);
        }
    }
    __syncwarp();

    if (lane < HEADS) {
        float wv = cutoff[e] * sh[wl][lane] * 0.12909944487358056f; // 1/sqrt(60)
        g_ew[(size_t)e * HEADS + lane] = __expf(wv);
    }
}

// ---------------------------------------------------------------------------
// Kernel 2: node-parallel gather of values. One warp per node.
// Loop body has NO syncwarp / NO shared memory: per edge, 4 independent
// LDG.128 of the v row + one 4B ew load (lane<8), shfl broadcast, register
// FMA accumulation. Iterations pipeline freely (loads of i+1 overlap i).
// ssum accumulated in-register -> no g_s, no separate normalize pass.
// ---------------------------------------------------------------------------
__global__ void __launch_bounds__(256)
gather_kernel(const float* __restrict__ v, float* __restrict__ out, int N) {
    int warp = (blockIdx.x * blockDim.x + threadIdx.x) >> 5;
    int lane = threadIdx.x & 31;
    if (warp >= N) return;

    int beg = g_rowstart[warp];
    int end = g_rowstart[warp + 1];

    // head owning each of this lane's 4 float4 slots (also the shfl src lane)
    int hl[4];
    #pragma unroll
    for (int t = 0; t < 4; t++) {
        int i4 = lane + 32 * t;
        hl[t] = head_of((i4 < 120 ? i4 : 119) * 4);
    }

    float4 acc[4];
    #pragma unroll
    for (int t = 0; t < 4; t++) acc[t] = make_float4(0.f, 0.f, 0.f, 0.f);
    float ssum = 0.0f;   // lane h (<8) accumulates sum of ew for head h

    #pragma unroll 2
    for (int i = beg; i < end; i++) {
        int e = g_perm[i];
        float ewl = (lane < HEADS) ? g_ew[(size_t)e * HEADS + lane] : 0.0f;
        const float4* v4 = (const float4*)(v + (size_t)e * DFUSED);

        #pragma unroll
        for (int t = 0; t < 4; t++) {
            float c = __shfl_sync(0xffffffffu, ewl, hl[t]);
            int i4 = lane + 32 * t;
            if (i4 < 120) {
                float4 vv = v4[i4];
                acc[t].x += c * vv.x;
                acc[t].y += c * vv.y;
                acc[t].z += c * vv.z;
                acc[t].w += c * vv.w;
            }
        }
        ssum += ewl;
    }

    // normalize + single coalesced write of the output row
    float4* o4 = (float4*)(out + (size_t)warp * DFUSED);
    #pragma unroll
    for (int t = 0; t < 4; t++) {
        float sv  = __shfl_sync(0xffffffffu, ssum, hl[t]);
        float inv = 1.0f / (sv + 1e-16f);
        int i4 = lane + 32 * t;
        if (i4 < 120) {
            float4 r;
            r.x = acc[t].x * inv; r.y = acc[t].y * inv;
            r.z = acc[t].z * inv; r.w = acc[t].w * inv;
            o4[i4] = r;
        }
    }
}

// ---------------------------------------------------------------------------
extern "C" void kernel_launch(void* const* d_in, const int* in_sizes, int n_in,
                              void* d_out, int out_size) {
    // Classify inputs by element count (robust to scalar inputs):
    //   3 buffers of size 480*E -> key, value, query (relative order preserved)
    //   1 buffer of size E      -> edge_weight_cutoff
    //   1 buffer of size 2*E    -> edge_index
    long long mx = 0;
    for (int i = 0; i < n_in; i++)
        if ((long long)in_sizes[i] > mx) mx = in_sizes[i];
    int E = (int)(mx / DFUSED);

    const float* big[3] = {0, 0, 0};
    const float* cutoff = 0;
    const void*  eidx   = 0;
    int nbig = 0;
    for (int i = 0; i < n_in; i++) {
        long long s = in_sizes[i];
        if (s == mx && nbig < 3)      big[nbig++] = (const float*)d_in[i];
        else if (s == (long long)E)   cutoff = (const float*)d_in[i];
        else if (s == 2LL * E)        eidx   = d_in[i];
    }
    const float* key   = big[0];
    const float* value = big[1];
    const float* query = big[2];

    int N = out_size / DFUSED;
    float* out = (float*)d_out;

    initA_kernel<<<64, 256>>>((const unsigned int*)eidx, E, N);
    hist_kernel<<<(E + 255) / 256, 256>>>(eidx, E, N);
    scan_kernel<<<1, 1024>>>(N);
    perm_kernel<<<(E + 255) / 256, 256>>>(eidx, E, N);
    logits_kernel<<<(E + 7) / 8, 256>>>(query, key, cutoff, E);
    gather_kernel<<<(N + 7) / 8, 256>>>(value, out, N);
}

// round 13
// speedup vs baseline: 1.0084x; 1.0017x over previous
#include <cuda_runtime.h>
#include <math.h>

#define HEADS   8
#define DFUSED  480
#define E_MAX   262144
#define N_MAX   16384

// Scratch (no device allocation allowed -> __device__ globals)
__device__ float g_ew[(size_t)E_MAX * HEADS];  // exp(w) per (edge, head)
__device__ int   g_cnt[N_MAX + 1];             // per-node edge counts
__device__ int   g_rowstart[N_MAX + 1];        // CSR row offsets
__device__ int   g_off[N_MAX];                 // atomic fill cursors
__device__ int   g_perm[E_MAX];                // edge ids grouped by dst node
__device__ int   g_is64;                       // edge_index dtype flag

// head of fused feature index j (block sizes 128/192/160; head strides 16/24/20)
__device__ __forceinline__ int head_of(int j) {
    return (j < 128) ? (j >> 4) : ((j < 320) ? (j - 128) / 24 : (j - 320) / 20);
}

// dtype-agnostic load of edge_index[1][e] (dst node), clamped to [0, N)
__device__ __forceinline__ int load_dst(const void* ei, int E, int e, int N) {
    int d;
    if (g_is64) d = (int)((const long long*)ei)[(size_t)E + e];
    else        d = ((const int*)ei)[E + e];
    d = d < 0 ? 0 : (d >= N ? N - 1 : d);
    return d;
}

// ---------------------------------------------------------------------------
// Kernel A: probe edge_index dtype (block 0) + zero g_cnt.
// int64 values < 2^31 -> int32 view has zeros at every odd word.
// ---------------------------------------------------------------------------
__global__ void initA_kernel(const unsigned int* __restrict__ ei, int E, int N) {
    if (blockIdx.x == 0) {
        __shared__ int nz;
        if (threadIdx.x == 0) nz = 0;
        __syncthreads();
        int lim = 2 * E < 512 ? 2 * E : 512;
        for (int i = threadIdx.x; i < lim; i += blockDim.x)
            if ((i & 1) && ei[i] != 0u) atomicAdd(&nz, 1);
        __syncthreads();
        if (threadIdx.x == 0) g_is64 = (nz == 0) ? 1 : 0;
    }
    int stride = gridDim.x * blockDim.x;
    for (int i = blockIdx.x * blockDim.x + threadIdx.x; i <= N; i += stride)
        g_cnt[i] = 0;
}

// ---------------------------------------------------------------------------
// Kernel B: histogram of destination nodes
// ---------------------------------------------------------------------------
__global__ void hist_kernel(const void* __restrict__ eidx, int E, int N) {
    int e = blockIdx.x * blockDim.x + threadIdx.x;
    if (e >= E) return;
    atomicAdd(&g_cnt[load_dst(eidx, E, e, N)], 1);
}

// ---------------------------------------------------------------------------
// Kernel C: exclusive scan of counts -> row offsets (single block, 1024 thr)
// ---------------------------------------------------------------------------
__global__ void __launch_bounds__(1024)
scan_kernel(int N) {
    __shared__ int wsum[32];
    __shared__ int s_total;
    int tid = threadIdx.x, lane = tid & 31, wid = tid >> 5;
    int running = 0;
    for (int base = 0; base < N; base += 1024) {
        int i = base + tid;
        int x = (i < N) ? g_cnt[i] : 0;
        int incl = x;
        #pragma unroll
        for (int d = 1; d < 32; d <<= 1) {
            int y = __shfl_up_sync(0xffffffffu, incl, d);
            if (lane >= d) incl += y;
        }
        if (lane == 31) wsum[wid] = incl;
        __syncthreads();
        if (wid == 0) {
            int w = wsum[lane], wi = w;
            #pragma unroll
            for (int d = 1; d < 32; d <<= 1) {
                int y = __shfl_up_sync(0xffffffffu, wi, d);
                if (lane >= d) wi += y;
            }
            wsum[lane] = wi - w;   // exclusive warp offset
        }
        __syncthreads();
        int excl = running + wsum[wid] + incl - x;
        if (i < N) { g_rowstart[i] = excl; g_off[i] = excl; }
        if (tid == 1023) s_total = excl + x;
        __syncthreads();
        running = s_total;
        __syncthreads();
    }
    if (tid == 0) g_rowstart[N] = running;
}

// ---------------------------------------------------------------------------
// Kernel D: permutation — edge ids grouped by destination node
// ---------------------------------------------------------------------------
__global__ void perm_kernel(const void* __restrict__ eidx, int E, int N) {
    int e = blockIdx.x * blockDim.x + threadIdx.x;
    if (e >= E) return;
    int pos = atomicAdd(&g_off[load_dst(eidx, E, e, N)], 1);
    g_perm[pos] = e;
}

// ---------------------------------------------------------------------------
// Kernel 1: edge-parallel logits — pure streaming, no atomics beyond smem.
// One warp per edge: read q,k rows (float4 coalesced), per-head dot via smem
// atomicAdd, write ew = exp(cutoff*dot/sqrt(60)) as 8 floats (32B store).
// Max-shift dropped: softmax is shift-invariant; logits here are O(5).
// ---------------------------------------------------------------------------
__global__ void __launch_bounds__(256)
logits_kernel(const float* __restrict__ q, const float* __restrict__ k,
              const float* __restrict__ cutoff, int E) {
    __shared__ float sh[8][HEADS];
    int e    = (blockIdx.x * blockDim.x + threadIdx.x) >> 5;
    int lane = threadIdx.x & 31;
    int wl   = threadIdx.x >> 5;
    if (e >= E) return;

    if (lane < HEADS) sh[wl][lane] = 0.0f;
    __syncwarp();

    const float4* q4 = (const float4*)(q + (size_t)e * DFUSED);
    const float4* k4 = (const float4*)(k + (size_t)e * DFUSED);

    #pragma unroll
    for (int t = 0; t < 4; t++) {
        int i4 = lane + 32 * t;
        if (i4 < 120) {
            float4 a = q4[i4];
            float4 b = k4[i4];
            float p = a.x * b.x + a.y * b.y + a.z * b.z + a.w * b.w;
            atomicAdd(&sh[wl][head_of(i4 * 4)], p);
        }
    }
    __syncwarp();

    if (lane < HEADS) {
        float wv = cutoff[e] * sh[wl][lane] * 0.12909944487358056f; // 1/sqrt(60)
        g_ew[(size_t)e * HEADS + lane] = __expf(wv);
    }
}

// ---------------------------------------------------------------------------
// Kernel 2: node-parallel gather of values. One warp per node.
// Loop body has NO syncwarp / NO shared memory: per edge, 4 independent
// LDG.128 of the v row + one 4B ew load (lane<8), shfl broadcast, register
// FMA accumulation. Iterations pipeline freely (loads of i+1 overlap i).
// ssum accumulated in-register -> no g_s, no separate normalize pass.
// ---------------------------------------------------------------------------
__global__ void __launch_bounds__(256)
gather_kernel(const float* __restrict__ v, float* __restrict__ out, int N) {
    int warp = (blockIdx.x * blockDim.x + threadIdx.x) >> 5;
    int lane = threadIdx.x & 31;
    if (warp >= N) return;

    int beg = g_rowstart[warp];
    int end = g_rowstart[warp + 1];

    // head owning each of this lane's 4 float4 slots (also the shfl src lane)
    int hl[4];
    #pragma unroll
    for (int t = 0; t < 4; t++) {
        int i4 = lane + 32 * t;
        hl[t] = head_of((i4 < 120 ? i4 : 119) * 4);
    }

    float4 acc[4];
    #pragma unroll
    for (int t = 0; t < 4; t++) acc[t] = make_float4(0.f, 0.f, 0.f, 0.f);
    float ssum = 0.0f;   // lane h (<8) accumulates sum of ew for head h

    #pragma unroll 2
    for (int i = beg; i < end; i++) {
        int e = g_perm[i];
        float ewl = (lane < HEADS) ? g_ew[(size_t)e * HEADS + lane] : 0.0f;
        const float4* v4 = (const float4*)(v + (size_t)e * DFUSED);

        #pragma unroll
        for (int t = 0; t < 4; t++) {
            float c = __shfl_sync(0xffffffffu, ewl, hl[t]);
            int i4 = lane + 32 * t;
            if (i4 < 120) {
                float4 vv = v4[i4];
                acc[t].x += c * vv.x;
                acc[t].y += c * vv.y;
                acc[t].z += c * vv.z;
                acc[t].w += c * vv.w;
            }
        }
        ssum += ewl;
    }

    // normalize + single coalesced write of the output row
    float4* o4 = (float4*)(out + (size_t)warp * DFUSED);
    #pragma unroll
    for (int t = 0; t < 4; t++) {
        float sv  = __shfl_sync(0xffffffffu, ssum, hl[t]);
        float inv = 1.0f / (sv + 1e-16f);
        int i4 = lane + 32 * t;
        if (i4 < 120) {
            float4 r;
            r.x = acc[t].x * inv; r.y = acc[t].y * inv;
            r.z = acc[t].z * inv; r.w = acc[t].w * inv;
            o4[i4] = r;
        }
    }
}

// ---------------------------------------------------------------------------
extern "C" void kernel_launch(void* const* d_in, const int* in_sizes, int n_in,
                              void* d_out, int out_size) {
    // Classify inputs by element count (robust to scalar inputs):
    //   3 buffers of size 480*E -> key, value, query (relative order preserved)
    //   1 buffer of size E      -> edge_weight_cutoff
    //   1 buffer of size 2*E    -> edge_index
    long long mx = 0;
    for (int i = 0; i < n_in; i++)
        if ((long long)in_sizes[i] > mx) mx = in_sizes[i];
    int E = (int)(mx / DFUSED);

    const float* big[3] = {0, 0, 0};
    const float* cutoff = 0;
    const void*  eidx   = 0;
    int nbig = 0;
    for (int i = 0; i < n_in; i++) {
        long long s = in_sizes[i];
        if (s == mx && nbig < 3)      big[nbig++] = (const float*)d_in[i];
        else if (s == (long long)E)   cutoff = (const float*)d_in[i];
        else if (s == 2LL * E)        eidx   = d_in[i];
    }
    const float* key   = big[0];
    const float* value = big[1];
    const float* query = big[2];

    int N = out_size / DFUSED;
    float* out = (float*)d_out;

    initA_kernel<<<64, 256>>>((const unsigned int*)eidx, E, N);
    hist_kernel<<<(E + 255) / 256, 256>>>(eidx, E, N);
    scan_kernel<<<1, 1024>>>(N);
    perm_kernel<<<(E + 255) / 256, 256>>>(eidx, E, N);
    logits_kernel<<<(E + 7) / 8, 256>>>(query, key, cutoff, E);
    gather_kernel<<<(N + 7) / 8, 256>>>(value, out, N);
}